// round 2
// baseline (speedup 1.0000x reference)
#include <cuda_runtime.h>
#include <cstdint>

// Z gate on qudits (0,5,10) of L=14 qubits (DIM=2): pure parity sign flip.
// x_real, x_imag: [N, B] float32, N=16384, B=2048.
// out: [2, N, B] float32 = {sign[n]*x_real, sign[n]*x_imag},
// sign[n] = (-1)^(bit13(n)+bit8(n)+bit3(n)).
//
// Implemented as sign-bit XOR on vectorized uint4 loads/stores. B=2048 floats
// per row => each 16B vector lies within one row; n = elem_idx / 2048.

static constexpr int N_ROWS = 16384;
static constexpr int B_COLS = 2048;
static constexpr long long TOTAL = (long long)N_ROWS * B_COLS;   // 33,554,432
static constexpr int TOTAL4 = (int)(TOTAL / 4);                  // 8,388,608

__global__ void __launch_bounds__(256)
z_phase_kernel(const uint4* __restrict__ xr,
               const uint4* __restrict__ xi,
               uint4* __restrict__ out_r,
               uint4* __restrict__ out_i)
{
    int idx = blockIdx.x * blockDim.x + threadIdx.x;   // float4 index
    if (idx >= TOTAL4) return;

    // element index = idx*4; row n = (idx*4) >> 11 = idx >> 9
    unsigned n = ((unsigned)idx) >> 9;
    unsigned parity = ((n >> 13) ^ (n >> 8) ^ (n >> 3)) & 1u;
    unsigned mask = parity << 31;   // 0 or 0x80000000 — flips float sign bit

    uint4 a = xr[idx];
    uint4 b = xi[idx];

    a.x ^= mask; a.y ^= mask; a.z ^= mask; a.w ^= mask;
    b.x ^= mask; b.y ^= mask; b.z ^= mask; b.w ^= mask;

    out_r[idx] = a;
    out_i[idx] = b;
}

extern "C" void kernel_launch(void* const* d_in, const int* in_sizes, int n_in,
                              void* d_out, int out_size)
{
    const uint4* xr = (const uint4*)d_in[0];
    const uint4* xi = (const uint4*)d_in[1];
    float* out = (float*)d_out;
    uint4* out_r = (uint4*)out;                 // [N, B] real part
    uint4* out_i = (uint4*)(out + TOTAL);       // [N, B] imag part

    const int threads = 256;
    const int blocks = (TOTAL4 + threads - 1) / threads;   // 32768
    z_phase_kernel<<<blocks, threads>>>(xr, xi, out_r, out_i);
}

// round 4
// speedup vs baseline: 1.0039x; 1.0039x over previous
#include <cuda_runtime.h>
#include <cstdint>

// Z gate (DIM=2) on qudits (0,5,10) of L=14: diagonal phase = parity sign flip.
// sign[n] = (-1)^(bit13(n) ^ bit8(n) ^ bit3(n)); out = [2,N,B] {±xr, ±xi}.
// Pure stream: sign-bit XOR on uint4 vectors, 4 vector-pairs per thread,
// front-batched loads (MLP=8) + streaming (.cs) cache hints.

static constexpr int N_ROWS = 16384;
static constexpr int B_COLS = 2048;
static constexpr long long TOTAL = (long long)N_ROWS * B_COLS;   // 33,554,432 floats
static constexpr int TOTAL4 = (int)(TOTAL / 4);                  // 8,388,608 uint4
static constexpr int ITEMS = 4;                                  // uint4-pairs per thread
static constexpr int THREADS = 256;
static constexpr int TILE = THREADS * ITEMS;                     // 1024 uint4 per block

__device__ __forceinline__ uint4 ldcs4(const uint4* p) {
    uint4 v;
    asm volatile("ld.global.cs.v4.u32 {%0,%1,%2,%3}, [%4];"
                 : "=r"(v.x), "=r"(v.y), "=r"(v.z), "=r"(v.w) : "l"(p));
    return v;
}
__device__ __forceinline__ void stcs4(uint4* p, uint4 v) {
    asm volatile("st.global.cs.v4.u32 [%0], {%1,%2,%3,%4};"
                 :: "l"(p), "r"(v.x), "r"(v.y), "r"(v.z), "r"(v.w) : "memory");
}

__global__ void __launch_bounds__(THREADS)
z_phase_kernel(const uint4* __restrict__ xr,
               const uint4* __restrict__ xi,
               uint4* __restrict__ out_r,
               uint4* __restrict__ out_i)
{
    int base = blockIdx.x * TILE + threadIdx.x;

    int idx[ITEMS];
    uint4 a[ITEMS], b[ITEMS];

    // Front-batched loads: 8 independent LDG.128 in flight before any store.
#pragma unroll
    for (int k = 0; k < ITEMS; k++) {
        idx[k] = base + k * THREADS;
        a[k] = ldcs4(xr + idx[k]);
    }
#pragma unroll
    for (int k = 0; k < ITEMS; k++)
        b[k] = ldcs4(xi + idx[k]);

#pragma unroll
    for (int k = 0; k < ITEMS; k++) {
        // element index = idx*4; row n = idx >> 9 (B=2048 floats/row)
        unsigned n = ((unsigned)idx[k]) >> 9;
        unsigned mask = (((n >> 13) ^ (n >> 8) ^ (n >> 3)) & 1u) << 31;
        a[k].x ^= mask; a[k].y ^= mask; a[k].z ^= mask; a[k].w ^= mask;
        b[k].x ^= mask; b[k].y ^= mask; b[k].z ^= mask; b[k].w ^= mask;
    }

#pragma unroll
    for (int k = 0; k < ITEMS; k++)
        stcs4(out_r + idx[k], a[k]);
#pragma unroll
    for (int k = 0; k < ITEMS; k++)
        stcs4(out_i + idx[k], b[k]);
}

extern "C" void kernel_launch(void* const* d_in, const int* in_sizes, int n_in,
                              void* d_out, int out_size)
{
    const uint4* xr = (const uint4*)d_in[0];
    const uint4* xi = (const uint4*)d_in[1];
    float* out = (float*)d_out;
    uint4* out_r = (uint4*)out;                 // [N, B] real part
    uint4* out_i = (uint4*)(out + TOTAL);       // [N, B] imag part

    const int blocks = TOTAL4 / TILE;           // 8192, exact (no tail)
    z_phase_kernel<<<blocks, THREADS>>>(xr, xi, out_r, out_i);
}